// round 2
// baseline (speedup 1.0000x reference)
#include <cuda_runtime.h>

#define B_  4
#define S_  2048
#define D_  1024
#define H_  16
#define DK_ 64
#define M_  (B_*S_)   // 8192 rows

// ---------------- scratch (device globals: no allocation allowed) ----------
__device__ float g_q  [(size_t)M_ * D_];
__device__ float g_k  [(size_t)M_ * D_];
__device__ float g_v  [(size_t)M_ * D_];
__device__ float g_att[(size_t)M_ * D_];

// ---------------- f32x2 packed helpers (full-rate fp32 on sm_103a) --------
typedef unsigned long long u64;

__device__ __forceinline__ u64 f32x2_dup(float a) {
    u64 r; asm("mov.b64 %0, {%1, %1};" : "=l"(r) : "f"(a)); return r;
}
__device__ __forceinline__ void f32x2_unpack(u64 v, float& lo, float& hi) {
    asm("mov.b64 {%0, %1}, %2;" : "=f"(lo), "=f"(hi) : "l"(v));
}
__device__ __forceinline__ void f32x2_fma(u64& d, u64 a, u64 b) {
    asm("fma.rn.f32x2 %0, %1, %2, %3;" : "=l"(d) : "l"(a), "l"(b), "l"(d));
}
__device__ __forceinline__ void f32x2_mul(u64& d, u64 a, u64 b) {
    asm("mul.rn.f32x2 %0, %1, %2;" : "=l"(d) : "l"(a), "l"(b));
}

// ---------------- SGEMM: C[M,1024] = A[M,1024] @ W[1024,1024] + bias -------
// 128x128 block tile, BK=8, 256 threads, 8x8 per thread, f32x2 accumulators.
__global__ __launch_bounds__(256, 2)
void sgemm_bias_kernel(const float* __restrict__ A, const float* __restrict__ W,
                       const float* __restrict__ bias, float* __restrict__ C)
{
    const int N = D_, K = D_;
    __shared__ float As[8][128];
    __shared__ float Bs[8][128];

    const int tid = threadIdx.x;
    const int tx  = tid & 15;        // 16 col-groups of 8
    const int ty  = tid >> 4;        // 16 row-groups of 8
    const int bx  = blockIdx.x;      // N tile
    const int by  = blockIdx.y;      // M tile

    const float* Ab = A + (size_t)by * 128 * K;
    const float* Wb = W + bx * 128;

    const int a_row = tid >> 1;            // 128 rows, 2 thr/row
    const int a_col = (tid & 1) * 4;       // float4 within BK=8
    const int b_row = tid >> 5;            // 8 k-rows
    const int b_col = (tid & 31) * 4;      // 128 cols via float4

    u64 acc[8][4];                          // 8 rows x 4 col-pairs
    #pragma unroll
    for (int i = 0; i < 8; i++)
        #pragma unroll
        for (int j = 0; j < 4; j++) acc[i][j] = 0ull;

    for (int k0 = 0; k0 < K; k0 += 8) {
        float4 a4 = *(const float4*)(Ab + (size_t)a_row * K + k0 + a_col);
        As[a_col + 0][a_row] = a4.x;
        As[a_col + 1][a_row] = a4.y;
        As[a_col + 2][a_row] = a4.z;
        As[a_col + 3][a_row] = a4.w;
        *(float4*)&Bs[b_row][b_col] =
            *(const float4*)(Wb + (size_t)(k0 + b_row) * N + b_col);
        __syncthreads();

        #pragma unroll
        for (int kk = 0; kk < 8; kk++) {
            float4 af0 = *(const float4*)&As[kk][ty * 8];
            float4 af1 = *(const float4*)&As[kk][ty * 8 + 4];
            ulonglong2 b01 = *(const ulonglong2*)&Bs[kk][tx * 8];
            ulonglong2 b23 = *(const ulonglong2*)&Bs[kk][tx * 8 + 4];
            u64 br[4] = {b01.x, b01.y, b23.x, b23.y};
            float ar[8] = {af0.x, af0.y, af0.z, af0.w, af1.x, af1.y, af1.z, af1.w};
            #pragma unroll
            for (int i = 0; i < 8; i++) {
                u64 a2 = f32x2_dup(ar[i]);
                #pragma unroll
                for (int j = 0; j < 4; j++) f32x2_fma(acc[i][j], a2, br[j]);
            }
        }
        __syncthreads();
    }

    const int crow0 = by * 128 + ty * 8;
    const int ccol0 = bx * 128 + tx * 8;
    float bb[8];
    {
        float4 bv0 = *(const float4*)(bias + ccol0);
        float4 bv1 = *(const float4*)(bias + ccol0 + 4);
        bb[0]=bv0.x; bb[1]=bv0.y; bb[2]=bv0.z; bb[3]=bv0.w;
        bb[4]=bv1.x; bb[5]=bv1.y; bb[6]=bv1.z; bb[7]=bv1.w;
    }
    #pragma unroll
    for (int i = 0; i < 8; i++) {
        float o[8];
        #pragma unroll
        for (int j = 0; j < 4; j++) {
            float lo, hi; f32x2_unpack(acc[i][j], lo, hi);
            o[2*j] = lo + bb[2*j]; o[2*j+1] = hi + bb[2*j+1];
        }
        float4 o0 = {o[0], o[1], o[2], o[3]};
        float4 o1 = {o[4], o[5], o[6], o[7]};
        float* cp = C + (size_t)(crow0 + i) * N + ccol0;
        *(float4*)cp       = o0;
        *(float4*)(cp + 4) = o1;
    }
}

// ---------------- causal flash attention, 64x64 tiles, fp32 ---------------
// grid (S/64, H, B), 256 threads. Thread (ty,tx): q-rows ty*4..+3,
// k-cols {tx, tx+16, tx+32, tx+48}, o d-cols tx*4..+3.
// K tile stored with XOR swizzle (granule ^= row&15) -> conflict-free LDS.128.
// P tile overlays the K tile (K reloaded each iteration anyway).
__global__ __launch_bounds__(256, 2)
void flash_kernel(const float* __restrict__ q, const float* __restrict__ k,
                  const float* __restrict__ v, float* __restrict__ o)
{
    __shared__ float Qs[64 * 64];
    __shared__ float Ks[64 * 64];
    __shared__ float Vs[64 * 64];
    float* Ps = Ks;   // overlay

    const int qt = blockIdx.x, h = blockIdx.y, b = blockIdx.z;
    const int tid = threadIdx.x;
    const int tx = tid & 15, ty = tid >> 4;

    const size_t base = (size_t)b * S_ * D_ + (size_t)h * DK_;
    const float* qg = q + base + (size_t)qt * 64 * D_;

    // load Q tile (64x64), straight layout
    for (int it = tid; it < 64 * 16; it += 256) {
        int r = it >> 4, c4 = (it & 15) << 2;
        *(float4*)&Qs[r * 64 + c4] = *(const float4*)(qg + (size_t)r * D_ + c4);
    }

    float m_i[4], l_i[4];
    u64 o2[4][2];
    #pragma unroll
    for (int i = 0; i < 4; i++) {
        m_i[i] = -1e30f; l_i[i] = 0.f; o2[i][0] = 0ull; o2[i][1] = 0ull;
    }

    for (int kt = 0; kt <= qt; kt++) {
        const float* kg = k + base + (size_t)kt * 64 * D_;
        const float* vg = v + base + (size_t)kt * 64 * D_;
        __syncthreads();   // prev PV done (and Q stores on first iter)
        for (int it = tid; it < 64 * 16; it += 256) {
            int r = it >> 4, c4 = it & 15;
            float4 kvv = *(const float4*)(kg + (size_t)r * D_ + (c4 << 2));
            Ks[r * 64 + (((c4 ^ (r & 15))) << 2) + 0] = kvv.x;
            Ks[r * 64 + (((c4 ^ (r & 15))) << 2) + 1] = kvv.y;
            Ks[r * 64 + (((c4 ^ (r & 15))) << 2) + 2] = kvv.z;
            Ks[r * 64 + (((c4 ^ (r & 15))) << 2) + 3] = kvv.w;
            *(float4*)&Vs[r * 64 + (c4 << 2)] =
                *(const float4*)(vg + (size_t)r * D_ + (c4 << 2));
        }
        __syncthreads();

        // ---- scores S = Q K^T (f32x2 over d-pairs) ----
        u64 s2[4][4];
        #pragma unroll
        for (int i = 0; i < 4; i++)
            #pragma unroll
            for (int j = 0; j < 4; j++) s2[i][j] = 0ull;

        #pragma unroll 4
        for (int d = 0; d < 64; d += 4) {
            ulonglong2 q2[4], k2[4];
            #pragma unroll
            for (int i = 0; i < 4; i++)
                q2[i] = *(const ulonglong2*)&Qs[(ty * 4 + i) * 64 + d];
            const int sgo = (((d >> 2) ^ tx) << 2);
            #pragma unroll
            for (int j = 0; j < 4; j++)
                k2[j] = *(const ulonglong2*)&Ks[(tx + 16 * j) * 64 + sgo];
            #pragma unroll
            for (int i = 0; i < 4; i++)
                #pragma unroll
                for (int j = 0; j < 4; j++) {
                    f32x2_fma(s2[i][j], q2[i].x, k2[j].x);
                    f32x2_fma(s2[i][j], q2[i].y, k2[j].y);
                }
        }
        __syncthreads();   // all K reads done before P overlays it

        float st[4][4];
        #pragma unroll
        for (int i = 0; i < 4; i++)
            #pragma unroll
            for (int j = 0; j < 4; j++) {
                float lo, hi; f32x2_unpack(s2[i][j], lo, hi);
                st[i][j] = (lo + hi) * 0.125f;   // 1/sqrt(64)
            }
        if (kt == qt) {
            #pragma unroll
            for (int i = 0; i < 4; i++)
                #pragma unroll
                for (int j = 0; j < 4; j++)
                    if (tx + 16 * j > ty * 4 + i) st[i][j] = -1e30f;
        }

        // ---- online softmax (row reductions via shfl over tx group) ----
        #pragma unroll
        for (int i = 0; i < 4; i++) {
            float tm = fmaxf(fmaxf(st[i][0], st[i][1]), fmaxf(st[i][2], st[i][3]));
            #pragma unroll
            for (int off = 8; off >= 1; off >>= 1)
                tm = fmaxf(tm, __shfl_xor_sync(0xffffffffu, tm, off));
            float mnew = fmaxf(m_i[i], tm);
            float corr = __expf(m_i[i] - mnew);
            m_i[i] = mnew;
            float rs = 0.f;
            #pragma unroll
            for (int j = 0; j < 4; j++) {
                float p = __expf(st[i][j] - mnew);
                Ps[(ty * 4 + i) * 64 + tx + 16 * j] = p;
                rs += p;
            }
            #pragma unroll
            for (int off = 8; off >= 1; off >>= 1)
                rs += __shfl_xor_sync(0xffffffffu, rs, off);
            l_i[i] = l_i[i] * corr + rs;
            u64 c2 = f32x2_dup(corr);
            f32x2_mul(o2[i][0], o2[i][0], c2);
            f32x2_mul(o2[i][1], o2[i][1], c2);
        }
        __syncthreads();   // P visible to all

        // ---- O += P V ----
        #pragma unroll 2
        for (int j4 = 0; j4 < 16; j4++) {
            float pr[4][4];
            #pragma unroll
            for (int i = 0; i < 4; i++) {
                float4 p4 = *(const float4*)&Ps[(ty * 4 + i) * 64 + (j4 << 2)];
                pr[i][0] = p4.x; pr[i][1] = p4.y; pr[i][2] = p4.z; pr[i][3] = p4.w;
            }
            #pragma unroll
            for (int jj = 0; jj < 4; jj++) {
                ulonglong2 vv = *(const ulonglong2*)&Vs[((j4 << 2) + jj) * 64 + (tx << 2)];
                #pragma unroll
                for (int i = 0; i < 4; i++) {
                    u64 p2 = f32x2_dup(pr[i][jj]);
                    f32x2_fma(o2[i][0], p2, vv.x);
                    f32x2_fma(o2[i][1], p2, vv.y);
                }
            }
        }
    }

    // ---- normalize + write ----
    float* og = o + base + (size_t)qt * 64 * D_;
    #pragma unroll
    for (int i = 0; i < 4; i++) {
        float inv = 1.f / l_i[i];
        float lo0, hi0, lo1, hi1;
        f32x2_unpack(o2[i][0], lo0, hi0);
        f32x2_unpack(o2[i][1], lo1, hi1);
        float4 res = {lo0 * inv, hi0 * inv, lo1 * inv, hi1 * inv};
        *(float4*)(og + (size_t)(ty * 4 + i) * D_ + (tx << 2)) = res;
    }
}

// ---------------- launch ---------------------------------------------------
extern "C" void kernel_launch(void* const* d_in, const int* in_sizes, int n_in,
                              void* d_out, int out_size)
{
    (void)in_sizes; (void)n_in; (void)out_size;
    const float* Qin  = (const float*)d_in[0];
    const float* KVin = (const float*)d_in[1];
    // d_in[2] = mask (causal by construction; handled analytically)
    const float* Wq = (const float*)d_in[3];
    const float* bq = (const float*)d_in[4];
    const float* Wk = (const float*)d_in[5];
    const float* bk = (const float*)d_in[6];
    const float* Wv = (const float*)d_in[7];
    const float* bv = (const float*)d_in[8];
    const float* Wo = (const float*)d_in[9];
    const float* bo = (const float*)d_in[10];
    float* out = (float*)d_out;

    float *gq, *gk, *gv, *ga;
    cudaGetSymbolAddress((void**)&gq, g_q);
    cudaGetSymbolAddress((void**)&gk, g_k);
    cudaGetSymbolAddress((void**)&gv, g_v);
    cudaGetSymbolAddress((void**)&ga, g_att);

    dim3 gg(D_ / 128, M_ / 128);
    sgemm_bias_kernel<<<gg, 256>>>(Qin,  Wq, bq, gq);
    sgemm_bias_kernel<<<gg, 256>>>(KVin, Wk, bk, gk);
    sgemm_bias_kernel<<<gg, 256>>>(KVin, Wv, bv, gv);

    dim3 fg(S_ / 64, H_, B_);
    flash_kernel<<<fg, 256>>>(gq, gk, gv, ga);

    sgemm_bias_kernel<<<gg, 256>>>(ga, Wo, bo, out);
}